// round 10
// baseline (speedup 1.0000x reference)
#include <cuda_runtime.h>
#include <cuda_bf16.h>
#include <cstdint>

#define Hd    1024
#define TSEQ  128
#define DIN   64
#define GRID  128
#define NTHR  256

#define NSTG      5
#define SLOT_SZ   40960                    // Ah 16K | Al 16K | Wh 4K | Wl 4K
#define DYN_SMEM  (NSTG * SLOT_SZ)        // 204800

#define BT(k) (128u * (unsigned)(k))

// ---------------- device globals (packed layouts; no allocation) ------------
__device__ __align__(1024) __nv_bfloat16 gPWih1[128][2][2048];       // [c][pl][32*64]
__device__ __align__(1024) __nv_bfloat16 gPWhh1[128][16][2][2048];
__device__ __align__(1024) __nv_bfloat16 gPWih2[128][16][2][2048];
__device__ __align__(1024) __nv_bfloat16 gPWhh2[128][16][2][2048];
__device__ __align__(1024) __nv_bfloat16 gPX[TSEQ][2][8192];         // [t][pl][64k*128b]
__device__ __align__(1024) __nv_bfloat16 gH1T[2][2][131072];         // [par][pl][1024k*128b]
__device__ __align__(1024) __nv_bfloat16 gH2T[2][2][131072];
__device__ __align__(1024) __nv_bfloat16 gOutT[2][8192];             // [pl][64k*128b]
__device__ float gH2f[128 * Hd];
__device__ float gOut[128 * DIN];
__device__ float gBias[2][4096];
__device__ unsigned g_bar_cnt;
__device__ volatile unsigned g_bar_gen;
__device__ unsigned g_ticket;              // monotonic split-barrier counter (reset at launch entry)

// ---------------- PTX helpers ------------------------------------------------
__device__ __forceinline__ uint32_t smem_u32(const void* p) {
    uint32_t a;
    asm("{ .reg .u64 t; cvta.to.shared.u64 t, %1; cvt.u32.u64 %0, t; }" : "=r"(a) : "l"(p));
    return a;
}
#define MBAR_INIT(a, c) \
    asm volatile("mbarrier.init.shared.b64 [%0], %1;" :: "r"(a), "r"((uint32_t)(c)) : "memory")
#define MBAR_ARRIVE(a) \
    asm volatile("mbarrier.arrive.shared.b64 _, [%0];" :: "r"(a) : "memory")
#define MBAR_EXPECT_TX(a, n) \
    asm volatile("mbarrier.arrive.expect_tx.shared.b64 _, [%0], %1;" :: "r"(a), "r"((uint32_t)(n)) : "memory")
#define MBAR_WAIT(a, ph) do { \
    uint32_t _m = (a), _p = (uint32_t)(ph), _d; \
    asm volatile("{\n\t.reg .pred p;\n\t" \
        "mbarrier.try_wait.parity.acquire.cta.shared::cta.b64 p, [%1], %2;\n\t" \
        "selp.b32 %0, 1, 0, p;\n\t}" : "=r"(_d) : "r"(_m), "r"(_p) : "memory"); \
    if (!_d) { \
        asm volatile("{\n\t.reg .pred P1;\n\t" \
            "WL_%=:\n\t" \
            "mbarrier.try_wait.parity.acquire.cta.shared::cta.b64 P1, [%0], %1, 0x989680;\n\t" \
            "@P1 bra.uni WD_%=;\n\tbra.uni WL_%=;\n\tWD_%=:\n\t}" \
            :: "r"(_m), "r"(_p) : "memory"); \
    } } while (0)
#define BULK_G2S(dst, src, sz, mb) \
    asm volatile("cp.async.bulk.shared::cta.global.mbarrier::complete_tx::bytes [%0], [%1], %2, [%3];" \
                 :: "r"(dst), "l"(src), "r"((uint32_t)(sz)), "r"(mb) : "memory")
#define LDSM4(r, a) \
    asm volatile("ldmatrix.sync.aligned.m8n8.x4.shared.b16 {%0,%1,%2,%3},[%4];" \
        : "=r"((r)[0]), "=r"((r)[1]), "=r"((r)[2]), "=r"((r)[3]) : "r"(a))
#define LDSM4T(r, a) \
    asm volatile("ldmatrix.sync.aligned.m8n8.x4.trans.shared.b16 {%0,%1,%2,%3},[%4];" \
        : "=r"((r)[0]), "=r"((r)[1]), "=r"((r)[2]), "=r"((r)[3]) : "r"(a))

__device__ __forceinline__ void mma16816(float* c, const uint32_t* a, uint32_t b0, uint32_t b1) {
    asm volatile("mma.sync.aligned.m16n8k16.row.col.f32.bf16.bf16.f32 "
                 "{%0,%1,%2,%3},{%4,%5,%6,%7},{%8,%9},{%0,%1,%2,%3};"
                 : "+f"(c[0]), "+f"(c[1]), "+f"(c[2]), "+f"(c[3])
                 : "r"(a[0]), "r"(a[1]), "r"(a[2]), "r"(a[3]), "r"(b0), "r"(b1));
}
__device__ __forceinline__ uint32_t sw128(uint32_t o) { return o ^ ((o >> 3) & 0x70); }
__device__ __forceinline__ uint32_t sw256(uint32_t o) { return o ^ ((o >> 4) & 0x70); }
__device__ __forceinline__ float sigm(float v) { return 1.0f / (1.0f + __expf(-v)); }
__device__ __forceinline__ float tanh_fast(float v) {      // exact sat at +/-inf
    return 1.0f - 2.0f / (__expf(2.0f * v) + 1.0f);
}

// ---------------- launch-entry classic barrier (also resets ticket) ----------
__device__ __forceinline__ void init_bar() {
    __syncthreads();
    if (threadIdx.x == 0) {
        unsigned gen = g_bar_gen;
        __threadfence();
        unsigned t = atomicAdd(&g_bar_cnt, 1u);
        if (t == GRID - 1) {
            g_ticket = 0;
            atomicExch(&g_bar_cnt, 0u);
            __threadfence();
            g_bar_gen = gen + 1;
        } else {
            while (g_bar_gen == gen) { __nanosleep(64); }
        }
        __threadfence();
    }
    __syncthreads();
}

// ---------------- split barrier primitives -----------------------------------
__device__ __forceinline__ void bar_arrive() {
    __threadfence();
    __syncthreads();
    if (threadIdx.x == 0) atomicAdd(&g_ticket, 1u);
}
__device__ __forceinline__ void wait_all(unsigned target) {
    if (threadIdx.x == 0) {
        while (*(volatile unsigned*)&g_ticket < target) __nanosleep(32);
    }
    __syncthreads();
    __threadfence();
}

// ---------------- pipeline ---------------------------------------------------
struct Cur { unsigned pi, ci; };
__shared__ __align__(8) uint64_t sFull[NSTG], sEmpty[NSTG];
__shared__ float sBias[64];

__device__ __forceinline__ void produce(Cur& C, uint32_t smb, char* const* src, unsigned dep) {
    const unsigned s = C.pi % NSTG;
    if (threadIdx.x == 0) {
        if (dep) {
            while (*(volatile unsigned*)&g_ticket < dep) __nanosleep(32);
            __threadfence();
        }
        MBAR_WAIT(smem_u32(&sEmpty[s]), 1 ^ ((C.pi / NSTG) & 1));
        const uint32_t mf = smem_u32(&sFull[s]);
        MBAR_EXPECT_TX(mf, SLOT_SZ);
        const uint32_t d = smb + s * SLOT_SZ;
        BULK_G2S(d,          src[0], 16384, mf);
        BULK_G2S(d + 16384,  src[1], 16384, mf);
        BULK_G2S(d + 32768,  src[2], 8192,  mf);
    }
    C.pi++;
}

__device__ __forceinline__ void consume(Cur& C, uint32_t smb, float acc[4][4]) {
    const unsigned s = C.ci % NSTG;
    MBAR_WAIT(smem_u32(&sFull[s]), (C.ci / NSTG) & 1);
    const uint32_t bA = smb + s * SLOT_SZ;
    const uint32_t bW = bA + 32768;
    const int lane = threadIdx.x & 31, w = threadIdx.x >> 5;
    const int kpart = ((lane >> 4) & 1) * 8 + (lane & 7);
    const int bsegA = (w << 5) + ((lane >> 3) & 1) * 16;
    const int nsub  = ((lane >> 4) & 1) * 8 + (lane & 7);
    const int khB   = ((lane >> 3) & 1) * 16;
#pragma unroll
    for (int ks = 0; ks < 4; ks++) {
        uint32_t ah[4], al[4], wh0[4], wh1[4], wl0[4], wl1[4];
        const uint32_t oA = sw256((uint32_t)((ks * 16 + kpart) * 256 + bsegA));
        LDSM4T(ah, bA + oA);
        LDSM4T(al, bA + 16384 + oA);
        const uint32_t o0 = sw128((uint32_t)(nsub * 128 + ks * 32 + khB));
        const uint32_t o1 = sw128((uint32_t)((16 + nsub) * 128 + ks * 32 + khB));
        LDSM4(wh0, bW + o0);  LDSM4(wh1, bW + o1);
        LDSM4(wl0, bW + 4096 + o0);  LDSM4(wl1, bW + 4096 + o1);
        if (ks == 3 && lane == 0) MBAR_ARRIVE(smem_u32(&sEmpty[s]));  // early slot release
        // pass-major order: RAW dep distance 4 per accumulator
        mma16816(acc[0], ah, wh0[0], wh0[1]);
        mma16816(acc[1], ah, wh0[2], wh0[3]);
        mma16816(acc[2], ah, wh1[0], wh1[1]);
        mma16816(acc[3], ah, wh1[2], wh1[3]);
        mma16816(acc[0], al, wh0[0], wh0[1]);
        mma16816(acc[1], al, wh0[2], wh0[3]);
        mma16816(acc[2], al, wh1[0], wh1[1]);
        mma16816(acc[3], al, wh1[2], wh1[3]);
        mma16816(acc[0], ah, wl0[0], wl0[1]);
        mma16816(acc[1], ah, wl0[2], wl0[3]);
        mma16816(acc[2], ah, wl1[0], wl1[1]);
        mma16816(acc[3], ah, wl1[2], wl1[3]);
    }
    C.ci++;
}

// ---------------- shuffle-only epilogue --------------------------------------
__device__ __forceinline__ void epilogue(float acc[4][4], const float* sB, float* cst,
                                         char* hhi, char* hlo, float* hf, int n0) {
    const int lane = threadIdx.x & 31, w = threadIdx.x >> 5;
    const int odd = lane & 1;
    const int b = 16 * w + (lane >> 2) + odd * 8;
    const int ubase = (lane & 3) >> 1;
#pragma unroll
    for (int nt = 0; nt < 4; nt++) {
        const float s0 = odd ? acc[nt][0] : acc[nt][2];
        const float s1 = odd ? acc[nt][1] : acc[nt][3];
        const float r0 = __shfl_xor_sync(0xffffffffu, s0, 1);
        const float r1 = __shfl_xor_sync(0xffffffffu, s1, 1);
        const float gi = odd ? r0 : acc[nt][0];
        const float gf = odd ? r1 : acc[nt][1];
        const float gg = odd ? acc[nt][2] : r0;
        const float go = odd ? acc[nt][3] : r1;
        const int u = 2 * nt + ubase;
        const float iv = gi + sB[u * 4 + 0];
        const float fv = gf + sB[u * 4 + 1];
        const float gv = gg + sB[u * 4 + 2];
        const float ov = go + sB[u * 4 + 3];
        const float cn = sigm(fv) * cst[nt] + sigm(iv) * tanh_fast(gv);
        cst[nt] = cn;
        const float h = sigm(ov) * tanh_fast(cn);
        const int n = n0 + u;
        const uint32_t sw = sw256((uint32_t)((n & 63) * 256 + b * 2)) + (n >> 6) * 16384;
        const __nv_bfloat16 hi = __float2bfloat16(h);
        *(__nv_bfloat16*)(hhi + sw) = hi;
        *(__nv_bfloat16*)(hlo + sw) = __float2bfloat16(h - __bfloat162float(hi));
        if (hf) hf[b * Hd + n] = h;
    }
}

// ---------------- output linear (K=1024 fp32) --------------------------------
__device__ void linear_out(const float* __restrict__ W, const float* __restrict__ bias, int c) {
    const int tid = threadIdx.x, d = tid >> 2, qt = tid & 3;
    const float* hb = gH2f + c * Hd + qt * 256;
    const float* wd = W + d * Hd + qt * 256;
    float s = 0.f;
#pragma unroll 8
    for (int k = 0; k < 256; k += 4) {
        const float4 hv = __ldcg((const float4*)(hb + k));
        const float4 wv = __ldg((const float4*)(wd + k));
        s += hv.x * wv.x + hv.y * wv.y + hv.z * wv.z + hv.w * wv.w;
    }
    s += __shfl_xor_sync(0xffffffffu, s, 1);
    s += __shfl_xor_sync(0xffffffffu, s, 2);
    if (qt == 0) {
        const float v = s + __ldg(bias + d);
        gOut[c * DIN + d] = v;
        const uint32_t sw = sw256((uint32_t)(d * 256 + c * 2));
        const __nv_bfloat16 hi = __float2bfloat16(v);
        *((__nv_bfloat16*)((char*)gOutT + sw)) = hi;
        *((__nv_bfloat16*)((char*)gOutT + 16384 + sw)) = __float2bfloat16(v - __bfloat162float(hi));
    }
}

// ---------------- chunk source resolution ------------------------------------
__device__ __forceinline__ void chunk_src(int j, char* x0, char* x1,
                                          char* h1p, char* h2p, char* h1n,
                                          const char* w1, const char* whh1,
                                          const char* whh2, const char* wih2,
                                          char* src[3]) {
    if (j == 0) { src[0] = x0; src[1] = x1; src[2] = (char*)w1; }
    else if (j < 17) { const int cc = j - 1;
        src[0] = h1p + cc * 16384; src[1] = h1p + 262144 + cc * 16384;
        src[2] = (char*)whh1 + cc * 8192; }
    else if (j < 33) { const int cc = j - 17;
        src[0] = h2p + cc * 16384; src[1] = h2p + 262144 + cc * 16384;
        src[2] = (char*)whh2 + cc * 8192; }
    else { const int cc = j - 33;
        src[0] = h1n + cc * 16384; src[1] = h1n + 262144 + cc * 16384;
        src[2] = (char*)wih2 + cc * 8192; }
}

// ---------------- one full LSTM step (49 chunks, 2 epilogues, 2 arrives) -----
__device__ void run_step(Cur& C, uint32_t smb, int n0,
                         char* x0, char* x1, char* h1p, char* h2p, char* h1n, char* h2n,
                         const char* w1, const char* whh1, const char* whh2, const char* wih2,
                         unsigned d0, unsigned d1, unsigned d17, unsigned d33,
                         float* c1s, float* c2s) {
    float acc[4][4];
#pragma unroll
    for (int i = 0; i < 4; i++)
#pragma unroll
        for (int j = 0; j < 4; j++) acc[i][j] = 0.f;
    char* src[3];
#pragma unroll
    for (int j = 0; j < 4; j++) {                 // prologue: fill 4 slots
        chunk_src(j, x0, x1, h1p, h2p, h1n, w1, whh1, whh2, wih2, src);
        produce(C, smb, src, j == 0 ? d0 : (j == 1 ? d1 : 0));
    }
    for (int i = 0; i < 49; i++) {
        const int j = i + 4;
        if (j < 49) {
            chunk_src(j, x0, x1, h1p, h2p, h1n, w1, whh1, whh2, wih2, src);
            produce(C, smb, src, j == 17 ? d17 : (j == 33 ? d33 : 0));
        }
        consume(C, smb, acc);
        if (i == 16) {
            epilogue(acc, sBias, c1s, h1n, h1n + 262144, nullptr, n0);
            bar_arrive();                         // B1[t]
#pragma unroll
            for (int a = 0; a < 4; a++)
#pragma unroll
                for (int bq = 0; bq < 4; bq++) acc[a][bq] = 0.f;
        }
    }
    epilogue(acc, sBias + 32, c2s, h2n, h2n + 262144, gH2f, n0);
    bar_arrive();                                 // B2[t]
}

// ---------------- precompute: repack into bulk-copyable layouts --------------
__device__ __forceinline__ void wsplit(float v, char* dsth, char* dstl, uint32_t off) {
    const __nv_bfloat16 h = __float2bfloat16(v);
    *(__nv_bfloat16*)(dsth + off) = h;
    *(__nv_bfloat16*)(dstl + off) = __float2bfloat16(v - __bfloat162float(h));
}
__device__ void packW(const float* __restrict__ W, int K, char* dst, int ncc, long t0, long nt) {
    const long tot = 128L * ncc * 2048;
    for (long i = t0; i < tot; i += nt) {
        const int c = (int)(i / (ncc * 2048));
        const int rem = (int)(i % (ncc * 2048));
        const int cc = rem >> 11, e = rem & 2047;
        const int np = e >> 6, k = e & 63;
        const float v = W[(long)((np & 3) * 1024 + c * 8 + (np >> 2)) * K + cc * 64 + k];
        const uint32_t sw = sw128((uint32_t)(np * 128 + k * 2));
        char* base = dst + ((long)(c * ncc + cc) * 2) * 4096;
        wsplit(v, base, base + 4096, sw);
    }
}
__global__ void precompute(
    const float* __restrict__ x,
    const float* __restrict__ Wih1, const float* __restrict__ Whh1,
    const float* __restrict__ bih1, const float* __restrict__ bhh1,
    const float* __restrict__ Wih2, const float* __restrict__ Whh2,
    const float* __restrict__ bih2, const float* __restrict__ bhh2)
{
    const long t0 = (long)blockIdx.x * blockDim.x + threadIdx.x;
    const long nt = (long)gridDim.x * blockDim.x;
    packW(Wih1, DIN, (char*)gPWih1, 1, t0, nt);
    packW(Whh1, Hd, (char*)gPWhh1, 16, t0, nt);
    packW(Wih2, Hd, (char*)gPWih2, 16, t0, nt);
    packW(Whh2, Hd, (char*)gPWhh2, 16, t0, nt);
    for (long i = t0; i < 128L * 8192; i += nt) {
        const int t = (int)(i >> 13), e = (int)(i & 8191);
        const int k = e >> 7, b = e & 127;
        const float v = x[(long)b * (TSEQ * DIN) + t * DIN + k];
        const uint32_t sw = sw256((uint32_t)(k * 256 + b * 2));
        char* base = (char*)gPX + (long)t * 32768;
        wsplit(v, base, base + 16384, sw);
    }
    for (long i = t0; i < 4096; i += nt) {
        gBias[0][i] = bih1[i] + bhh1[i];
        gBias[1][i] = bih2[i] + bhh2[i];
    }
}

// ---------------- persistent fused kernel ------------------------------------
__global__ void __launch_bounds__(NTHR, 1) lstm_hmma(
    const float* __restrict__ Wlin, const float* __restrict__ blin,
    const float* __restrict__ Whio, const float* __restrict__ bhio,
    const int* __restrict__ futp, float* __restrict__ out)
{
    extern __shared__ __align__(128) char dyn[];
    const uint32_t smb = smem_u32(dyn);
    const int tid = threadIdx.x, c = blockIdx.x;
    const int n0 = c * 8;

    if (tid == 0) {
#pragma unroll
        for (int s = 0; s < NSTG; s++) {
            MBAR_INIT(smem_u32(&sFull[s]), 1);
            MBAR_INIT(smem_u32(&sEmpty[s]), 8);   // one arrival per warp
        }
    }
    if (tid < 64) {
        const int l = tid >> 5, np = tid & 31;
        sBias[tid] = gBias[l][(np & 3) * 1024 + n0 + (np >> 2)];
    }
    {   // zero parity-0 h planes
        char* bases[4] = { (char*)gH1T, (char*)gH1T + 262144,
                           (char*)gH2T, (char*)gH2T + 262144 };
        const uint32_t off = (uint32_t)(c >> 3) * 16384 + ((8 * c) & 63) * 256;
#pragma unroll
        for (int a = 0; a < 4; a++)
            *(uint64_t*)(bases[a] + off + tid * 8) = 0ULL;
    }
    const int fut = *futp;
    __syncthreads();
    init_bar();                                   // also resets g_ticket

    Cur C; C.pi = 0; C.ci = 0;
    float c1s[4], c2s[4];
#pragma unroll
    for (int q = 0; q < 4; q++) { c1s[q] = 0.f; c2s[q] = 0.f; }
    int p = 0;

    const char* whh1b = (const char*)gPWhh1 + (long)c * 16 * 8192;
    const char* whh2b = (const char*)gPWhh2 + (long)c * 16 * 8192;
    const char* wih2b = (const char*)gPWih2 + (long)c * 16 * 8192;
    const char* w1b   = (const char*)gPWih1 + (long)c * 8192;

    for (int t = 0; t < TSEQ; t++) {
        char* h1p = (char*)gH1T + p * 524288;
        char* h1n = (char*)gH1T + (1 - p) * 524288;
        char* h2p = (char*)gH2T + p * 524288;
        char* h2n = (char*)gH2T + (1 - p) * 524288;
        run_step(C, smb, n0,
                 (char*)gPX + (long)t * 32768, (char*)gPX + (long)t * 32768 + 16384,
                 h1p, h2p, h1n, h2n, w1b, whh1b, whh2b, wih2b,
                 0u, t ? BT(2 * t - 1) : 0u, t ? BT(2 * t) : 0u, BT(2 * t + 1),
                 c1s, c2s);
        p ^= 1;
    }

    wait_all(BT(2 * TSEQ));                       // B2[127]
    linear_out(Wlin, blin, c);
    bar_arrive();                                 // Lin0 = event 257

    for (int f = 0; f < fut; f++) {
        char* h1p = (char*)gH1T + p * 524288;
        char* h1n = (char*)gH1T + (1 - p) * 524288;
        char* h2p = (char*)gH2T + p * 524288;
        char* h2n = (char*)gH2T + (1 - p) * 524288;
        run_step(C, smb, n0,
                 (char*)gOutT, (char*)gOutT + 16384,
                 h1p, h2p, h1n, h2n, w1b, whh1b, whh2b, wih2b,
                 BT(257 + 3 * f), BT(255 + 3 * f), BT(256 + 3 * f), BT(258 + 3 * f),
                 c1s, c2s);
        p ^= 1;
        wait_all(BT(259 + 3 * f));                // B2 of this future step
        linear_out(Whio, bhio, c);
        bar_arrive();                             // Lin_{f+1}
    }

    __syncthreads();
    for (int d = tid; d < DIN; d += NTHR)
        out[c * DIN + d] = gOut[c * DIN + d];
}

extern "C" void kernel_launch(void* const* d_in, const int* in_sizes, int n_in,
                              void* d_out, int out_size)
{
    const float* x    = (const float*)d_in[0];
    const float* Wih1 = (const float*)d_in[1];
    const float* Whh1 = (const float*)d_in[2];
    const float* bih1 = (const float*)d_in[3];
    const float* bhh1 = (const float*)d_in[4];
    const float* Wih2 = (const float*)d_in[5];
    const float* Whh2 = (const float*)d_in[6];
    const float* bih2 = (const float*)d_in[7];
    const float* bhh2 = (const float*)d_in[8];
    const float* Wlin = (const float*)d_in[9];
    const float* blin = (const float*)d_in[10];
    const float* Whio = (const float*)d_in[11];
    const float* bhio = (const float*)d_in[12];
    const int*   futp = (const int*)d_in[13];

    cudaFuncSetAttribute(lstm_hmma, cudaFuncAttributeMaxDynamicSharedMemorySize, DYN_SMEM);

    precompute<<<1024, 256>>>(x, Wih1, Whh1, bih1, bhh1, Wih2, Whh2, bih2, bhh2);
    lstm_hmma<<<GRID, NTHR, DYN_SMEM>>>(Wlin, blin, Whio, bhio, futp, (float*)d_out);
}

// round 11
// speedup vs baseline: 1.7691x; 1.7691x over previous
#include <cuda_runtime.h>
#include <cuda_bf16.h>
#include <cuda_fp16.h>
#include <cstdint>

#define Hd    1024
#define TSEQ  128
#define DIN   64
#define GRID  128
#define NTHR  256

#define NSTG      8
#define SLOT_SZ   24576                    // A 16K | Wh 4K | Wl 4K
#define DYN_SMEM  (NSTG * SLOT_SZ)        // 196608

#define BT(k) (128u * (unsigned)(k))

// ---------------- device globals (packed fp16 layouts; no allocation) -------
__device__ __align__(1024) __half gPWih1[128][2][2048];       // [c][pl][32*64]
__device__ __align__(1024) __half gPWhh1[128][16][2][2048];
__device__ __align__(1024) __half gPWih2[128][16][2][2048];
__device__ __align__(1024) __half gPWhh2[128][16][2][2048];
__device__ __align__(1024) __half gPX[TSEQ][8192];            // [t][64k*128b]
__device__ __align__(1024) __half gH1T[2][131072];            // [par][1024k*128b]
__device__ __align__(1024) __half gH2T[2][131072];
__device__ __align__(1024) __half gOutT[8192];                // [64k*128b]
__device__ float gH2f[128 * Hd];
__device__ float gOut[128 * DIN];
__device__ float gBias[2][4096];
__device__ unsigned g_bar_cnt;
__device__ volatile unsigned g_bar_gen;
__device__ unsigned g_ticket;              // monotonic split-barrier counter

// ---------------- PTX helpers ------------------------------------------------
__device__ __forceinline__ uint32_t smem_u32(const void* p) {
    uint32_t a;
    asm("{ .reg .u64 t; cvta.to.shared.u64 t, %1; cvt.u32.u64 %0, t; }" : "=r"(a) : "l"(p));
    return a;
}
#define MBAR_INIT(a, c) \
    asm volatile("mbarrier.init.shared.b64 [%0], %1;" :: "r"(a), "r"((uint32_t)(c)) : "memory")
#define MBAR_ARRIVE(a) \
    asm volatile("mbarrier.arrive.shared.b64 _, [%0];" :: "r"(a) : "memory")
#define MBAR_EXPECT_TX(a, n) \
    asm volatile("mbarrier.arrive.expect_tx.shared.b64 _, [%0], %1;" :: "r"(a), "r"((uint32_t)(n)) : "memory")
#define MBAR_WAIT(a, ph) do { \
    uint32_t _m = (a), _p = (uint32_t)(ph), _d; \
    asm volatile("{\n\t.reg .pred p;\n\t" \
        "mbarrier.try_wait.parity.acquire.cta.shared::cta.b64 p, [%1], %2;\n\t" \
        "selp.b32 %0, 1, 0, p;\n\t}" : "=r"(_d) : "r"(_m), "r"(_p) : "memory"); \
    if (!_d) { \
        asm volatile("{\n\t.reg .pred P1;\n\t" \
            "WL_%=:\n\t" \
            "mbarrier.try_wait.parity.acquire.cta.shared::cta.b64 P1, [%0], %1, 0x989680;\n\t" \
            "@P1 bra.uni WD_%=;\n\tbra.uni WL_%=;\n\tWD_%=:\n\t}" \
            :: "r"(_m), "r"(_p) : "memory"); \
    } } while (0)
#define BULK_G2S(dst, src, sz, mb) \
    asm volatile("cp.async.bulk.shared::cta.global.mbarrier::complete_tx::bytes [%0], [%1], %2, [%3];" \
                 :: "r"(dst), "l"(src), "r"((uint32_t)(sz)), "r"(mb) : "memory")
#define LDSM4(r, a) \
    asm volatile("ldmatrix.sync.aligned.m8n8.x4.shared.b16 {%0,%1,%2,%3},[%4];" \
        : "=r"((r)[0]), "=r"((r)[1]), "=r"((r)[2]), "=r"((r)[3]) : "r"(a))
#define LDSM4T(r, a) \
    asm volatile("ldmatrix.sync.aligned.m8n8.x4.trans.shared.b16 {%0,%1,%2,%3},[%4];" \
        : "=r"((r)[0]), "=r"((r)[1]), "=r"((r)[2]), "=r"((r)[3]) : "r"(a))

__device__ __forceinline__ void mma16816(float* c, const uint32_t* a, uint32_t b0, uint32_t b1) {
    asm volatile("mma.sync.aligned.m16n8k16.row.col.f32.f16.f16.f32 "
                 "{%0,%1,%2,%3},{%4,%5,%6,%7},{%8,%9},{%0,%1,%2,%3};"
                 : "+f"(c[0]), "+f"(c[1]), "+f"(c[2]), "+f"(c[3])
                 : "r"(a[0]), "r"(a[1]), "r"(a[2]), "r"(a[3]), "r"(b0), "r"(b1));
}
__device__ __forceinline__ uint32_t sw128(uint32_t o) { return o ^ ((o >> 3) & 0x70); }
__device__ __forceinline__ uint32_t sw256(uint32_t o) { return o ^ ((o >> 4) & 0x70); }
__device__ __forceinline__ float sigm(float v) { return 1.0f / (1.0f + __expf(-v)); }
__device__ __forceinline__ float tanh_fast(float v) {
    return 1.0f - 2.0f / (__expf(2.0f * v) + 1.0f);
}

// ---------------- launch-entry classic barrier (also resets ticket) ----------
__device__ __forceinline__ void init_bar() {
    __syncthreads();
    if (threadIdx.x == 0) {
        unsigned gen = g_bar_gen;
        __threadfence();
        unsigned t = atomicAdd(&g_bar_cnt, 1u);
        if (t == GRID - 1) {
            g_ticket = 0;
            atomicExch(&g_bar_cnt, 0u);
            __threadfence();
            g_bar_gen = gen + 1;
        } else {
            while (g_bar_gen == gen) { __nanosleep(64); }
        }
        __threadfence();
    }
    __syncthreads();
}

// ---------------- split barrier primitives -----------------------------------
__device__ __forceinline__ void bar_arrive() {
    __threadfence();
    __syncthreads();
    if (threadIdx.x == 0) atomicAdd(&g_ticket, 1u);
}
__device__ __forceinline__ void wait_all(unsigned target) {
    if (threadIdx.x == 0) {
        while (*(volatile unsigned*)&g_ticket < target) __nanosleep(32);
    }
    __syncthreads();
    __threadfence();
}

// ---------------- pipeline ---------------------------------------------------
struct Cur { unsigned pi, ci; };
__shared__ __align__(8) uint64_t sFull[NSTG], sEmpty[NSTG];
__shared__ float sBias[64];

__device__ __forceinline__ void produce(Cur& C, uint32_t smb, char* const* src, unsigned dep) {
    const unsigned s = C.pi % NSTG;
    if (threadIdx.x == 0) {
        if (dep) {
            while (*(volatile unsigned*)&g_ticket < dep) __nanosleep(32);
            __threadfence();
        }
        MBAR_WAIT(smem_u32(&sEmpty[s]), 1 ^ ((C.pi / NSTG) & 1));
        const uint32_t mf = smem_u32(&sFull[s]);
        MBAR_EXPECT_TX(mf, SLOT_SZ);
        const uint32_t d = smb + s * SLOT_SZ;
        BULK_G2S(d,          src[0], 16384, mf);   // A (single fp16 plane)
        BULK_G2S(d + 16384,  src[1], 4096,  mf);   // W hi
        BULK_G2S(d + 20480,  src[2], 4096,  mf);   // W lo
    }
    C.pi++;
}

__device__ __forceinline__ void consume(Cur& C, uint32_t smb, float acc[4][4]) {
    const unsigned s = C.ci % NSTG;
    MBAR_WAIT(smem_u32(&sFull[s]), (C.ci / NSTG) & 1);
    const uint32_t bA = smb + s * SLOT_SZ;
    const uint32_t bW = bA + 16384;
    const int lane = threadIdx.x & 31, w = threadIdx.x >> 5;
    const int kpart = ((lane >> 4) & 1) * 8 + (lane & 7);
    const int bsegA = (w << 5) + ((lane >> 3) & 1) * 16;
    const int nsub  = ((lane >> 4) & 1) * 8 + (lane & 7);
    const int khB   = ((lane >> 3) & 1) * 16;
#pragma unroll
    for (int ks = 0; ks < 4; ks++) {
        uint32_t a4[4], wh0[4], wh1[4], wl0[4], wl1[4];
        const uint32_t oA = sw256((uint32_t)((ks * 16 + kpart) * 256 + bsegA));
        LDSM4T(a4, bA + oA);
        const uint32_t o0 = sw128((uint32_t)(nsub * 128 + ks * 32 + khB));
        const uint32_t o1 = sw128((uint32_t)((16 + nsub) * 128 + ks * 32 + khB));
        LDSM4(wh0, bW + o0);  LDSM4(wh1, bW + o1);
        LDSM4(wl0, bW + 4096 + o0);  LDSM4(wl1, bW + 4096 + o1);
        mma16816(acc[0], a4, wh0[0], wh0[1]);
        mma16816(acc[1], a4, wh0[2], wh0[3]);
        mma16816(acc[2], a4, wh1[0], wh1[1]);
        mma16816(acc[3], a4, wh1[2], wh1[3]);
        mma16816(acc[0], a4, wl0[0], wl0[1]);
        mma16816(acc[1], a4, wl0[2], wl0[3]);
        mma16816(acc[2], a4, wl1[0], wl1[1]);
        mma16816(acc[3], a4, wl1[2], wl1[3]);
    }
    if ((threadIdx.x & 31) == 0) MBAR_ARRIVE(smem_u32(&sEmpty[s]));
    C.ci++;
}

// ---------------- shuffle-only epilogue (single fp16 h-plane) ----------------
__device__ __forceinline__ void epilogue(float acc[4][4], const float* sB, float* cst,
                                         char* hpl, float* hf, int n0) {
    const int lane = threadIdx.x & 31, w = threadIdx.x >> 5;
    const int odd = lane & 1;
    const int b = 16 * w + (lane >> 2) + odd * 8;
    const int ubase = (lane & 3) >> 1;
#pragma unroll
    for (int nt = 0; nt < 4; nt++) {
        const float s0 = odd ? acc[nt][0] : acc[nt][2];
        const float s1 = odd ? acc[nt][1] : acc[nt][3];
        const float r0 = __shfl_xor_sync(0xffffffffu, s0, 1);
        const float r1 = __shfl_xor_sync(0xffffffffu, s1, 1);
        const float gi = odd ? r0 : acc[nt][0];
        const float gf = odd ? r1 : acc[nt][1];
        const float gg = odd ? acc[nt][2] : r0;
        const float go = odd ? acc[nt][3] : r1;
        const int u = 2 * nt + ubase;
        const float iv = gi + sB[u * 4 + 0];
        const float fv = gf + sB[u * 4 + 1];
        const float gv = gg + sB[u * 4 + 2];
        const float ov = go + sB[u * 4 + 3];
        const float cn = sigm(fv) * cst[nt] + sigm(iv) * tanh_fast(gv);
        cst[nt] = cn;
        const float h = sigm(ov) * tanh_fast(cn);
        const int n = n0 + u;
        const uint32_t sw = sw256((uint32_t)((n & 63) * 256 + b * 2)) + (n >> 6) * 16384;
        *(__half*)(hpl + sw) = __float2half_rn(h);
        if (hf) hf[b * Hd + n] = h;
    }
}

// ---------------- output linear (K=1024 fp32) --------------------------------
__device__ void linear_out(const float* __restrict__ W, const float* __restrict__ bias, int c) {
    const int tid = threadIdx.x, d = tid >> 2, qt = tid & 3;
    const float* hb = gH2f + c * Hd + qt * 256;
    const float* wd = W + d * Hd + qt * 256;
    float s = 0.f;
#pragma unroll 8
    for (int k = 0; k < 256; k += 4) {
        const float4 hv = __ldcg((const float4*)(hb + k));
        const float4 wv = __ldg((const float4*)(wd + k));
        s += hv.x * wv.x + hv.y * wv.y + hv.z * wv.z + hv.w * wv.w;
    }
    s += __shfl_xor_sync(0xffffffffu, s, 1);
    s += __shfl_xor_sync(0xffffffffu, s, 2);
    if (qt == 0) {
        const float v = s + __ldg(bias + d);
        gOut[c * DIN + d] = v;
        const uint32_t sw = sw256((uint32_t)(d * 256 + c * 2));
        *(__half*)((char*)gOutT + sw) = __float2half_rn(v);
    }
}

// ---------------- chunk source resolution ------------------------------------
__device__ __forceinline__ void chunk_src(int j, char* x0,
                                          char* h1p, char* h2p, char* h1n,
                                          const char* w1, const char* whh1,
                                          const char* whh2, const char* wih2,
                                          char* src[3]) {
    if (j == 0) { src[0] = x0; src[1] = (char*)w1; src[2] = (char*)w1 + 4096; }
    else if (j < 17) { const int cc = j - 1;
        src[0] = h1p + cc * 16384;
        src[1] = (char*)whh1 + cc * 8192; src[2] = (char*)whh1 + cc * 8192 + 4096; }
    else if (j < 33) { const int cc = j - 17;
        src[0] = h2p + cc * 16384;
        src[1] = (char*)whh2 + cc * 8192; src[2] = (char*)whh2 + cc * 8192 + 4096; }
    else { const int cc = j - 33;
        src[0] = h1n + cc * 16384;
        src[1] = (char*)wih2 + cc * 8192; src[2] = (char*)wih2 + cc * 8192 + 4096; }
}

// ---------------- one full LSTM step (49 chunks, 2 epilogues, 2 arrives) -----
__device__ void run_step(Cur& C, uint32_t smb, int n0,
                         char* x0, char* h1p, char* h2p, char* h1n, char* h2n,
                         const char* w1, const char* whh1, const char* whh2, const char* wih2,
                         unsigned d0, unsigned d1, unsigned d17, unsigned d33,
                         float* c1s, float* c2s) {
    float acc[4][4];
#pragma unroll
    for (int i = 0; i < 4; i++)
#pragma unroll
        for (int j = 0; j < 4; j++) acc[i][j] = 0.f;
    char* src[3];
#pragma unroll
    for (int j = 0; j < 7; j++) {                 // prologue: fill 7 of 8 slots
        chunk_src(j, x0, h1p, h2p, h1n, w1, whh1, whh2, wih2, src);
        produce(C, smb, src, j == 0 ? d0 : (j == 1 ? d1 : 0));
    }
    for (int i = 0; i < 49; i++) {
        const int j = i + 7;
        if (j < 49) {
            chunk_src(j, x0, h1p, h2p, h1n, w1, whh1, whh2, wih2, src);
            produce(C, smb, src, j == 17 ? d17 : (j == 33 ? d33 : 0));
        }
        consume(C, smb, acc);
        if (i == 16) {
            epilogue(acc, sBias, c1s, h1n, nullptr, n0);
            bar_arrive();                         // B1[t]
#pragma unroll
            for (int a = 0; a < 4; a++)
#pragma unroll
                for (int bq = 0; bq < 4; bq++) acc[a][bq] = 0.f;
        }
    }
    epilogue(acc, sBias + 32, c2s, h2n, gH2f, n0);
    bar_arrive();                                 // B2[t]
}

// ---------------- precompute: fp16 hi/lo repack ------------------------------
__device__ __forceinline__ void wsplit(float v, char* dsth, char* dstl, uint32_t off) {
    const __half h = __float2half_rn(v);
    *(__half*)(dsth + off) = h;
    *(__half*)(dstl + off) = __float2half_rn(v - __half2float(h));
}
__device__ void packW(const float* __restrict__ W, int K, char* dst, int ncc, long t0, long nt) {
    const long tot = 128L * ncc * 2048;
    for (long i = t0; i < tot; i += nt) {
        const int c = (int)(i / (ncc * 2048));
        const int rem = (int)(i % (ncc * 2048));
        const int cc = rem >> 11, e = rem & 2047;
        const int np = e >> 6, k = e & 63;
        const float v = W[(long)((np & 3) * 1024 + c * 8 + (np >> 2)) * K + cc * 64 + k];
        const uint32_t sw = sw128((uint32_t)(np * 128 + k * 2));
        char* base = dst + ((long)(c * ncc + cc) * 2) * 4096;
        wsplit(v, base, base + 4096, sw);
    }
}
__global__ void precompute(
    const float* __restrict__ x,
    const float* __restrict__ Wih1, const float* __restrict__ Whh1,
    const float* __restrict__ bih1, const float* __restrict__ bhh1,
    const float* __restrict__ Wih2, const float* __restrict__ Whh2,
    const float* __restrict__ bih2, const float* __restrict__ bhh2)
{
    const long t0 = (long)blockIdx.x * blockDim.x + threadIdx.x;
    const long nt = (long)gridDim.x * blockDim.x;
    packW(Wih1, DIN, (char*)gPWih1, 1, t0, nt);
    packW(Whh1, Hd, (char*)gPWhh1, 16, t0, nt);
    packW(Wih2, Hd, (char*)gPWih2, 16, t0, nt);
    packW(Whh2, Hd, (char*)gPWhh2, 16, t0, nt);
    for (long i = t0; i < 128L * 8192; i += nt) {
        const int t = (int)(i >> 13), e = (int)(i & 8191);
        const int k = e >> 7, b = e & 127;
        const float v = x[(long)b * (TSEQ * DIN) + t * DIN + k];
        const uint32_t sw = sw256((uint32_t)(k * 256 + b * 2));
        *(__half*)((char*)gPX + (long)t * 16384 + sw) = __float2half_rn(v);
    }
    for (long i = t0; i < 4096; i += nt) {
        gBias[0][i] = bih1[i] + bhh1[i];
        gBias[1][i] = bih2[i] + bhh2[i];
    }
}

// ---------------- persistent fused kernel ------------------------------------
__global__ void __launch_bounds__(NTHR, 1) lstm_hmma(
    const float* __restrict__ Wlin, const float* __restrict__ blin,
    const float* __restrict__ Whio, const float* __restrict__ bhio,
    const int* __restrict__ futp, float* __restrict__ out)
{
    extern __shared__ __align__(128) char dyn[];
    const uint32_t smb = smem_u32(dyn);
    const int tid = threadIdx.x, c = blockIdx.x;
    const int n0 = c * 8;

    if (tid == 0) {
#pragma unroll
        for (int s = 0; s < NSTG; s++) {
            MBAR_INIT(smem_u32(&sFull[s]), 1);
            MBAR_INIT(smem_u32(&sEmpty[s]), 8);   // one arrival per warp
        }
    }
    if (tid < 64) {
        const int l = tid >> 5, np = tid & 31;
        sBias[tid] = gBias[l][(np & 3) * 1024 + n0 + (np >> 2)];
    }
    {   // zero parity-0 h planes (this CTA's 8 k-rows, both layers)
        char* bases[2] = { (char*)gH1T, (char*)gH2T };
        const uint32_t off = (uint32_t)(c >> 3) * 16384 + ((8 * c) & 63) * 256;
#pragma unroll
        for (int a = 0; a < 2; a++)
            *(uint64_t*)(bases[a] + off + tid * 8) = 0ULL;
    }
    const int fut = *futp;
    __syncthreads();
    init_bar();                                   // also resets g_ticket

    Cur C; C.pi = 0; C.ci = 0;
    float c1s[4], c2s[4];
#pragma unroll
    for (int q = 0; q < 4; q++) { c1s[q] = 0.f; c2s[q] = 0.f; }
    int p = 0;

    const char* whh1b = (const char*)gPWhh1 + (long)c * 16 * 8192;
    const char* whh2b = (const char*)gPWhh2 + (long)c * 16 * 8192;
    const char* wih2b = (const char*)gPWih2 + (long)c * 16 * 8192;
    const char* w1b   = (const char*)gPWih1 + (long)c * 8192;

    for (int t = 0; t < TSEQ; t++) {
        char* h1p = (char*)gH1T + p * 262144;
        char* h1n = (char*)gH1T + (1 - p) * 262144;
        char* h2p = (char*)gH2T + p * 262144;
        char* h2n = (char*)gH2T + (1 - p) * 262144;
        run_step(C, smb, n0,
                 (char*)gPX + (long)t * 16384,
                 h1p, h2p, h1n, h2n, w1b, whh1b, whh2b, wih2b,
                 0u, t ? BT(2 * t - 1) : 0u, t ? BT(2 * t) : 0u, BT(2 * t + 1),
                 c1s, c2s);
        p ^= 1;
    }

    wait_all(BT(2 * TSEQ));                       // B2[127]
    linear_out(Wlin, blin, c);
    bar_arrive();                                 // Lin0 = event 257

    for (int f = 0; f < fut; f++) {
        char* h1p = (char*)gH1T + p * 262144;
        char* h1n = (char*)gH1T + (1 - p) * 262144;
        char* h2p = (char*)gH2T + p * 262144;
        char* h2n = (char*)gH2T + (1 - p) * 262144;
        run_step(C, smb, n0,
                 (char*)gOutT,
                 h1p, h2p, h1n, h2n, w1b, whh1b, whh2b, wih2b,
                 BT(257 + 3 * f), BT(255 + 3 * f), BT(256 + 3 * f), BT(258 + 3 * f),
                 c1s, c2s);
        p ^= 1;
        wait_all(BT(259 + 3 * f));                // B2 of this future step
        linear_out(Whio, bhio, c);
        bar_arrive();                             // Lin_{f+1}
    }

    __syncthreads();
    for (int d = tid; d < DIN; d += NTHR)
        out[c * DIN + d] = gOut[c * DIN + d];
}

extern "C" void kernel_launch(void* const* d_in, const int* in_sizes, int n_in,
                              void* d_out, int out_size)
{
    const float* x    = (const float*)d_in[0];
    const float* Wih1 = (const float*)d_in[1];
    const float* Whh1 = (const float*)d_in[2];
    const float* bih1 = (const float*)d_in[3];
    const float* bhh1 = (const float*)d_in[4];
    const float* Wih2 = (const float*)d_in[5];
    const float* Whh2 = (const float*)d_in[6];
    const float* bih2 = (const float*)d_in[7];
    const float* bhh2 = (const float*)d_in[8];
    const float* Wlin = (const float*)d_in[9];
    const float* blin = (const float*)d_in[10];
    const float* Whio = (const float*)d_in[11];
    const float* bhio = (const float*)d_in[12];
    const int*   futp = (const int*)d_in[13];

    cudaFuncSetAttribute(lstm_hmma, cudaFuncAttributeMaxDynamicSharedMemorySize, DYN_SMEM);

    precompute<<<1024, 256>>>(x, Wih1, Whh1, bih1, bhh1, Wih2, Whh2, bih2, bhh2);
    lstm_hmma<<<GRID, NTHR, DYN_SMEM>>>(Wlin, blin, Whio, bhio, futp, (float*)d_out);
}

// round 12
// speedup vs baseline: 1.9900x; 1.1249x over previous
#include <cuda_runtime.h>
#include <cuda_bf16.h>
#include <cuda_fp16.h>
#include <cstdint>

#define Hd    1024
#define TSEQ  128
#define DIN   64
#define GRID  128
#define NTHR  256

#define NSTG      8
#define SLOT_SZ   24576                    // A 16K | Wh 4K | Wl 4K
#define DYN_SMEM  (NSTG * SLOT_SZ)        // 196608

#define BT(k) (128u * (unsigned)(k))

// ---------------- device globals (packed fp16 layouts; no allocation) -------
__device__ __align__(1024) __half gPWih1[128][2][2048];       // [c][pl][32*64]
__device__ __align__(1024) __half gPWhh1[128][16][2][2048];
__device__ __align__(1024) __half gPWih2[128][16][2][2048];
__device__ __align__(1024) __half gPWhh2[128][16][2][2048];
__device__ __align__(1024) __half gPX[TSEQ][8192];            // [t][64k*128b]
__device__ __align__(1024) __half gH1T[2][131072];            // [par][1024k*128b]
__device__ __align__(1024) __half gH2T[2][131072];
__device__ __align__(1024) __half gOutT[8192];                // [64k*128b]
__device__ float gH2f[128 * Hd];
__device__ float gOut[128 * DIN];
__device__ float gBias[2][4096];
__device__ unsigned g_bar_cnt;
__device__ volatile unsigned g_bar_gen;
__device__ unsigned g_ticket;              // monotonic split-barrier counter

// ---------------- PTX helpers ------------------------------------------------
__device__ __forceinline__ uint32_t smem_u32(const void* p) {
    uint32_t a;
    asm("{ .reg .u64 t; cvta.to.shared.u64 t, %1; cvt.u32.u64 %0, t; }" : "=r"(a) : "l"(p));
    return a;
}
#define MBAR_INIT(a, c) \
    asm volatile("mbarrier.init.shared.b64 [%0], %1;" :: "r"(a), "r"((uint32_t)(c)) : "memory")
#define MBAR_ARRIVE(a) \
    asm volatile("mbarrier.arrive.shared.b64 _, [%0];" :: "r"(a) : "memory")
#define MBAR_EXPECT_TX(a, n) \
    asm volatile("mbarrier.arrive.expect_tx.shared.b64 _, [%0], %1;" :: "r"(a), "r"((uint32_t)(n)) : "memory")
#define MBAR_WAIT(a, ph) do { \
    uint32_t _m = (a), _p = (uint32_t)(ph), _d; \
    asm volatile("{\n\t.reg .pred p;\n\t" \
        "mbarrier.try_wait.parity.acquire.cta.shared::cta.b64 p, [%1], %2;\n\t" \
        "selp.b32 %0, 1, 0, p;\n\t}" : "=r"(_d) : "r"(_m), "r"(_p) : "memory"); \
    if (!_d) { \
        asm volatile("{\n\t.reg .pred P1;\n\t" \
            "WL_%=:\n\t" \
            "mbarrier.try_wait.parity.acquire.cta.shared::cta.b64 P1, [%0], %1, 0x989680;\n\t" \
            "@P1 bra.uni WD_%=;\n\tbra.uni WL_%=;\n\tWD_%=:\n\t}" \
            :: "r"(_m), "r"(_p) : "memory"); \
    } } while (0)
#define BULK_G2S(dst, src, sz, mb) \
    asm volatile("cp.async.bulk.shared::cta.global.mbarrier::complete_tx::bytes [%0], [%1], %2, [%3];" \
                 :: "r"(dst), "l"(src), "r"((uint32_t)(sz)), "r"(mb) : "memory")
#define LDSM4(r, a) \
    asm volatile("ldmatrix.sync.aligned.m8n8.x4.shared.b16 {%0,%1,%2,%3},[%4];" \
        : "=r"((r)[0]), "=r"((r)[1]), "=r"((r)[2]), "=r"((r)[3]) : "r"(a))
#define LDSM4T(r, a) \
    asm volatile("ldmatrix.sync.aligned.m8n8.x4.trans.shared.b16 {%0,%1,%2,%3},[%4];" \
        : "=r"((r)[0]), "=r"((r)[1]), "=r"((r)[2]), "=r"((r)[3]) : "r"(a))

__device__ __forceinline__ void mma16816(float* c, const uint32_t* a, uint32_t b0, uint32_t b1) {
    asm volatile("mma.sync.aligned.m16n8k16.row.col.f32.f16.f16.f32 "
                 "{%0,%1,%2,%3},{%4,%5,%6,%7},{%8,%9},{%0,%1,%2,%3};"
                 : "+f"(c[0]), "+f"(c[1]), "+f"(c[2]), "+f"(c[3])
                 : "r"(a[0]), "r"(a[1]), "r"(a[2]), "r"(a[3]), "r"(b0), "r"(b1));
}
__device__ __forceinline__ uint32_t sw128(uint32_t o) { return o ^ ((o >> 3) & 0x70); }
__device__ __forceinline__ uint32_t sw256(uint32_t o) { return o ^ ((o >> 4) & 0x70); }
__device__ __forceinline__ float sigm(float v) { return 1.0f / (1.0f + __expf(-v)); }
__device__ __forceinline__ float tanh_fast(float v) {
    return 1.0f - 2.0f / (__expf(2.0f * v) + 1.0f);
}

// ---------------- launch-entry classic barrier (also resets ticket) ----------
__device__ __forceinline__ void init_bar() {
    __syncthreads();
    if (threadIdx.x == 0) {
        unsigned gen = g_bar_gen;
        __threadfence();
        unsigned t = atomicAdd(&g_bar_cnt, 1u);
        if (t == GRID - 1) {
            g_ticket = 0;
            atomicExch(&g_bar_cnt, 0u);
            __threadfence();
            g_bar_gen = gen + 1;
        } else {
            while (g_bar_gen == gen) { __nanosleep(64); }
        }
        __threadfence();
    }
    __syncthreads();
}

// ---------------- split barrier primitives -----------------------------------
__device__ __forceinline__ void bar_arrive() {
    __threadfence();
    __syncthreads();
    if (threadIdx.x == 0) atomicAdd(&g_ticket, 1u);
}
__device__ __forceinline__ void wait_all(unsigned target) {
    if (threadIdx.x == 0) {
        while (*(volatile unsigned*)&g_ticket < target) __nanosleep(32);
    }
    __syncthreads();
    __threadfence();
}

// ---------------- pipeline ---------------------------------------------------
struct Cur { unsigned pi, ci; };
__shared__ __align__(8) uint64_t sFull[NSTG], sEmpty[NSTG];
__shared__ float sBias[64];

__device__ __forceinline__ void produce(Cur& C, uint32_t smb, char* const* src, unsigned dep) {
    const unsigned s = C.pi % NSTG;
    if (threadIdx.x == 0) {
        if (dep) {
            while (*(volatile unsigned*)&g_ticket < dep) __nanosleep(32);
            __threadfence();
        }
        MBAR_WAIT(smem_u32(&sEmpty[s]), 1 ^ ((C.pi / NSTG) & 1));
        const uint32_t mf = smem_u32(&sFull[s]);
        MBAR_EXPECT_TX(mf, SLOT_SZ);
        const uint32_t d = smb + s * SLOT_SZ;
        BULK_G2S(d,          src[0], 16384, mf);   // A (single fp16 plane)
        BULK_G2S(d + 16384,  src[1], 4096,  mf);   // W hi
        BULK_G2S(d + 20480,  src[2], 4096,  mf);   // W lo
    }
    C.pi++;
}

// single-chunk consume (used for the odd 17th chunk of layer 1)
__device__ __forceinline__ void consume(Cur& C, uint32_t smb, float acc[4][4]) {
    const unsigned s = C.ci % NSTG;
    MBAR_WAIT(smem_u32(&sFull[s]), (C.ci / NSTG) & 1);
    const uint32_t bA = smb + s * SLOT_SZ;
    const uint32_t bW = bA + 16384;
    const int lane = threadIdx.x & 31, w = threadIdx.x >> 5;
    const int kpart = ((lane >> 4) & 1) * 8 + (lane & 7);
    const int bsegA = (w << 5) + ((lane >> 3) & 1) * 16;
    const int nsub  = ((lane >> 4) & 1) * 8 + (lane & 7);
    const int khB   = ((lane >> 3) & 1) * 16;
#pragma unroll
    for (int ks = 0; ks < 4; ks++) {
        uint32_t a4[4], wh0[4], wh1[4], wl0[4], wl1[4];
        const uint32_t oA = sw256((uint32_t)((ks * 16 + kpart) * 256 + bsegA));
        LDSM4T(a4, bA + oA);
        const uint32_t o0 = sw128((uint32_t)(nsub * 128 + ks * 32 + khB));
        const uint32_t o1 = sw128((uint32_t)((16 + nsub) * 128 + ks * 32 + khB));
        LDSM4(wh0, bW + o0);  LDSM4(wh1, bW + o1);
        LDSM4(wl0, bW + 4096 + o0);  LDSM4(wl1, bW + 4096 + o1);
        mma16816(acc[0], a4, wh0[0], wh0[1]);
        mma16816(acc[1], a4, wh0[2], wh0[3]);
        mma16816(acc[2], a4, wh1[0], wh1[1]);
        mma16816(acc[3], a4, wh1[2], wh1[3]);
        mma16816(acc[0], a4, wl0[0], wl0[1]);
        mma16816(acc[1], a4, wl0[2], wl0[3]);
        mma16816(acc[2], a4, wl1[0], wl1[1]);
        mma16816(acc[3], a4, wl1[2], wl1[3]);
    }
    if ((threadIdx.x & 31) == 0) MBAR_ARRIVE(smem_u32(&sEmpty[s]));
    C.ci++;
}

// dual-chunk consume: two slots in flight, interleaved -> 2x ILP per warp
__device__ __forceinline__ void consume2(Cur& C, uint32_t smb,
                                         float accA[4][4], float accB[4][4]) {
    const unsigned i0 = C.ci, i1 = C.ci + 1;
    const unsigned s0 = i0 % NSTG, s1 = i1 % NSTG;
    MBAR_WAIT(smem_u32(&sFull[s0]), (i0 / NSTG) & 1);
    MBAR_WAIT(smem_u32(&sFull[s1]), (i1 / NSTG) & 1);
    const uint32_t bA0 = smb + s0 * SLOT_SZ, bW0 = bA0 + 16384;
    const uint32_t bA1 = smb + s1 * SLOT_SZ, bW1 = bA1 + 16384;
    const int lane = threadIdx.x & 31, w = threadIdx.x >> 5;
    const int kpart = ((lane >> 4) & 1) * 8 + (lane & 7);
    const int bsegA = (w << 5) + ((lane >> 3) & 1) * 16;
    const int nsub  = ((lane >> 4) & 1) * 8 + (lane & 7);
    const int khB   = ((lane >> 3) & 1) * 16;
#pragma unroll
    for (int ks = 0; ks < 4; ks++) {
        uint32_t aA[4], whA0[4], whA1[4], wlA0[4], wlA1[4];
        uint32_t aB[4], whB0[4], whB1[4], wlB0[4], wlB1[4];
        const uint32_t oA = sw256((uint32_t)((ks * 16 + kpart) * 256 + bsegA));
        const uint32_t o0 = sw128((uint32_t)(nsub * 128 + ks * 32 + khB));
        const uint32_t o1 = sw128((uint32_t)((16 + nsub) * 128 + ks * 32 + khB));
        LDSM4T(aA, bA0 + oA);
        LDSM4T(aB, bA1 + oA);
        LDSM4(whA0, bW0 + o0);  LDSM4(whA1, bW0 + o1);
        LDSM4(whB0, bW1 + o0);  LDSM4(whB1, bW1 + o1);
        LDSM4(wlA0, bW0 + 4096 + o0);  LDSM4(wlA1, bW0 + 4096 + o1);
        LDSM4(wlB0, bW1 + 4096 + o0);  LDSM4(wlB1, bW1 + 4096 + o1);
        // bank-alternating, pass-major: same-accumulator dep distance = 8
        mma16816(accA[0], aA, whA0[0], whA0[1]);
        mma16816(accA[1], aA, whA0[2], whA0[3]);
        mma16816(accA[2], aA, whA1[0], whA1[1]);
        mma16816(accA[3], aA, whA1[2], whA1[3]);
        mma16816(accB[0], aB, whB0[0], whB0[1]);
        mma16816(accB[1], aB, whB0[2], whB0[3]);
        mma16816(accB[2], aB, whB1[0], whB1[1]);
        mma16816(accB[3], aB, whB1[2], whB1[3]);
        mma16816(accA[0], aA, wlA0[0], wlA0[1]);
        mma16816(accA[1], aA, wlA0[2], wlA0[3]);
        mma16816(accA[2], aA, wlA1[0], wlA1[1]);
        mma16816(accA[3], aA, wlA1[2], wlA1[3]);
        mma16816(accB[0], aB, wlB0[0], wlB0[1]);
        mma16816(accB[1], aB, wlB0[2], wlB0[3]);
        mma16816(accB[2], aB, wlB1[0], wlB1[1]);
        mma16816(accB[3], aB, wlB1[2], wlB1[3]);
    }
    if ((threadIdx.x & 31) == 0) {
        MBAR_ARRIVE(smem_u32(&sEmpty[s0]));
        MBAR_ARRIVE(smem_u32(&sEmpty[s1]));
    }
    C.ci += 2;
}

// ---------------- shuffle-only epilogue (single fp16 h-plane) ----------------
__device__ __forceinline__ void epilogue(float acc[4][4], const float* sB, float* cst,
                                         char* hpl, float* hf, int n0) {
    const int lane = threadIdx.x & 31, w = threadIdx.x >> 5;
    const int odd = lane & 1;
    const int b = 16 * w + (lane >> 2) + odd * 8;
    const int ubase = (lane & 3) >> 1;
#pragma unroll
    for (int nt = 0; nt < 4; nt++) {
        const float s0 = odd ? acc[nt][0] : acc[nt][2];
        const float s1 = odd ? acc[nt][1] : acc[nt][3];
        const float r0 = __shfl_xor_sync(0xffffffffu, s0, 1);
        const float r1 = __shfl_xor_sync(0xffffffffu, s1, 1);
        const float gi = odd ? r0 : acc[nt][0];
        const float gf = odd ? r1 : acc[nt][1];
        const float gg = odd ? acc[nt][2] : r0;
        const float go = odd ? acc[nt][3] : r1;
        const int u = 2 * nt + ubase;
        const float iv = gi + sB[u * 4 + 0];
        const float fv = gf + sB[u * 4 + 1];
        const float gv = gg + sB[u * 4 + 2];
        const float ov = go + sB[u * 4 + 3];
        const float cn = sigm(fv) * cst[nt] + sigm(iv) * tanh_fast(gv);
        cst[nt] = cn;
        const float h = sigm(ov) * tanh_fast(cn);
        const int n = n0 + u;
        const uint32_t sw = sw256((uint32_t)((n & 63) * 256 + b * 2)) + (n >> 6) * 16384;
        *(__half*)(hpl + sw) = __float2half_rn(h);
        if (hf) hf[b * Hd + n] = h;
    }
}

// ---------------- output linear (K=1024 fp32) --------------------------------
__device__ void linear_out(const float* __restrict__ W, const float* __restrict__ bias, int c) {
    const int tid = threadIdx.x, d = tid >> 2, qt = tid & 3;
    const float* hb = gH2f + c * Hd + qt * 256;
    const float* wd = W + d * Hd + qt * 256;
    float s = 0.f;
#pragma unroll 8
    for (int k = 0; k < 256; k += 4) {
        const float4 hv = __ldcg((const float4*)(hb + k));
        const float4 wv = __ldg((const float4*)(wd + k));
        s += hv.x * wv.x + hv.y * wv.y + hv.z * wv.z + hv.w * wv.w;
    }
    s += __shfl_xor_sync(0xffffffffu, s, 1);
    s += __shfl_xor_sync(0xffffffffu, s, 2);
    if (qt == 0) {
        const float v = s + __ldg(bias + d);
        gOut[c * DIN + d] = v;
        const uint32_t sw = sw256((uint32_t)(d * 256 + c * 2));
        *(__half*)((char*)gOutT + sw) = __float2half_rn(v);
    }
}

// ---------------- chunk source resolution ------------------------------------
__device__ __forceinline__ void chunk_src(int j, char* x0,
                                          char* h1p, char* h2p, char* h1n,
                                          const char* w1, const char* whh1,
                                          const char* whh2, const char* wih2,
                                          char* src[3]) {
    if (j == 0) { src[0] = x0; src[1] = (char*)w1; src[2] = (char*)w1 + 4096; }
    else if (j < 17) { const int cc = j - 1;
        src[0] = h1p + cc * 16384;
        src[1] = (char*)whh1 + cc * 8192; src[2] = (char*)whh1 + cc * 8192 + 4096; }
    else if (j < 33) { const int cc = j - 17;
        src[0] = h2p + cc * 16384;
        src[1] = (char*)whh2 + cc * 8192; src[2] = (char*)whh2 + cc * 8192 + 4096; }
    else { const int cc = j - 33;
        src[0] = h1n + cc * 16384;
        src[1] = (char*)wih2 + cc * 8192; src[2] = (char*)wih2 + cc * 8192 + 4096; }
}
__device__ __forceinline__ unsigned chunk_dep(int j, unsigned d0, unsigned d1,
                                              unsigned d17, unsigned d33) {
    return j == 0 ? d0 : (j == 1 ? d1 : (j == 17 ? d17 : (j == 33 ? d33 : 0u)));
}

// ---------------- one full LSTM step -----------------------------------------
// Layer 1 = chunks 0..16 (8 pairs + 1 single), layer 2 = chunks 17..48 (16 pairs).
// Produce schedule keeps in-flight <= NSTG and never blocks tid0 on its own
// unconsumed slots: prologue 6, then 2 produces before each consume2.
__device__ void run_step(Cur& C, uint32_t smb, int n0,
                         char* x0, char* h1p, char* h2p, char* h1n, char* h2n,
                         const char* w1, const char* whh1, const char* whh2, const char* wih2,
                         unsigned d0, unsigned d1, unsigned d17, unsigned d33,
                         float* c1s, float* c2s) {
    float accA[4][4], accB[4][4];
#pragma unroll
    for (int i = 0; i < 4; i++)
#pragma unroll
        for (int j = 0; j < 4; j++) { accA[i][j] = 0.f; accB[i][j] = 0.f; }
    char* src[3];
#pragma unroll
    for (int j = 0; j < 6; j++) {                 // prologue: 6 chunks
        chunk_src(j, x0, h1p, h2p, h1n, w1, whh1, whh2, wih2, src);
        produce(C, smb, src, chunk_dep(j, d0, d1, d17, d33));
    }
    for (int k = 0; k < 8; k++) {                 // layer-1 pairs (chunks 0..15)
#pragma unroll
        for (int q = 0; q < 2; q++) {
            const int j = 6 + 2 * k + q;
            chunk_src(j, x0, h1p, h2p, h1n, w1, whh1, whh2, wih2, src);
            produce(C, smb, src, chunk_dep(j, d0, d1, d17, d33));
        }
        consume2(C, smb, accA, accB);
    }
    consume(C, smb, accA);                        // chunk 16
#pragma unroll
    for (int i = 0; i < 4; i++)
#pragma unroll
        for (int j = 0; j < 4; j++) accA[i][j] += accB[i][j];
    epilogue(accA, sBias, c1s, h1n, nullptr, n0);
    bar_arrive();                                 // B1[t]
#pragma unroll
    for (int i = 0; i < 4; i++)
#pragma unroll
        for (int j = 0; j < 4; j++) { accA[i][j] = 0.f; accB[i][j] = 0.f; }

    for (int k = 0; k < 16; k++) {                // layer-2 pairs (chunks 17..48)
#pragma unroll
        for (int q = 0; q < 2; q++) {
            const int j = 22 + 2 * k + q;
            if (j <= 48) {
                chunk_src(j, x0, h1p, h2p, h1n, w1, whh1, whh2, wih2, src);
                produce(C, smb, src, chunk_dep(j, d0, d1, d17, d33));
            }
        }
        consume2(C, smb, accA, accB);
    }
#pragma unroll
    for (int i = 0; i < 4; i++)
#pragma unroll
        for (int j = 0; j < 4; j++) accA[i][j] += accB[i][j];
    epilogue(accA, sBias + 32, c2s, h2n, gH2f, n0);
    bar_arrive();                                 // B2[t]
}

// ---------------- precompute: fp16 hi/lo repack ------------------------------
__device__ __forceinline__ void wsplit(float v, char* dsth, char* dstl, uint32_t off) {
    const __half h = __float2half_rn(v);
    *(__half*)(dsth + off) = h;
    *(__half*)(dstl + off) = __float2half_rn(v - __half2float(h));
}
__device__ void packW(const float* __restrict__ W, int K, char* dst, int ncc, long t0, long nt) {
    const long tot = 128L * ncc * 2048;
    for (long i = t0; i < tot; i += nt) {
        const int c = (int)(i / (ncc * 2048));
        const int rem = (int)(i % (ncc * 2048));
        const int cc = rem >> 11, e = rem & 2047;
        const int np = e >> 6, k = e & 63;
        const float v = W[(long)((np & 3) * 1024 + c * 8 + (np >> 2)) * K + cc * 64 + k];
        const uint32_t sw = sw128((uint32_t)(np * 128 + k * 2));
        char* base = dst + ((long)(c * ncc + cc) * 2) * 4096;
        wsplit(v, base, base + 4096, sw);
    }
}
__global__ void precompute(
    const float* __restrict__ x,
    const float* __restrict__ Wih1, const float* __restrict__ Whh1,
    const float* __restrict__ bih1, const float* __restrict__ bhh1,
    const float* __restrict__ Wih2, const float* __restrict__ Whh2,
    const float* __restrict__ bih2, const float* __restrict__ bhh2)
{
    const long t0 = (long)blockIdx.x * blockDim.x + threadIdx.x;
    const long nt = (long)gridDim.x * blockDim.x;
    packW(Wih1, DIN, (char*)gPWih1, 1, t0, nt);
    packW(Whh1, Hd, (char*)gPWhh1, 16, t0, nt);
    packW(Wih2, Hd, (char*)gPWih2, 16, t0, nt);
    packW(Whh2, Hd, (char*)gPWhh2, 16, t0, nt);
    for (long i = t0; i < 128L * 8192; i += nt) {
        const int t = (int)(i >> 13), e = (int)(i & 8191);
        const int k = e >> 7, b = e & 127;
        const float v = x[(long)b * (TSEQ * DIN) + t * DIN + k];
        const uint32_t sw = sw256((uint32_t)(k * 256 + b * 2));
        *(__half*)((char*)gPX + (long)t * 16384 + sw) = __float2half_rn(v);
    }
    for (long i = t0; i < 4096; i += nt) {
        gBias[0][i] = bih1[i] + bhh1[i];
        gBias[1][i] = bih2[i] + bhh2[i];
    }
}

// ---------------- persistent fused kernel ------------------------------------
__global__ void __launch_bounds__(NTHR, 1) lstm_hmma(
    const float* __restrict__ Wlin, const float* __restrict__ blin,
    const float* __restrict__ Whio, const float* __restrict__ bhio,
    const int* __restrict__ futp, float* __restrict__ out)
{
    extern __shared__ __align__(128) char dyn[];
    const uint32_t smb = smem_u32(dyn);
    const int tid = threadIdx.x, c = blockIdx.x;
    const int n0 = c * 8;

    if (tid == 0) {
#pragma unroll
        for (int s = 0; s < NSTG; s++) {
            MBAR_INIT(smem_u32(&sFull[s]), 1);
            MBAR_INIT(smem_u32(&sEmpty[s]), 8);   // one arrival per warp
        }
    }
    if (tid < 64) {
        const int l = tid >> 5, np = tid & 31;
        sBias[tid] = gBias[l][(np & 3) * 1024 + n0 + (np >> 2)];
    }
    {   // zero parity-0 h planes (this CTA's 8 k-rows, both layers)
        char* bases[2] = { (char*)gH1T, (char*)gH2T };
        const uint32_t off = (uint32_t)(c >> 3) * 16384 + ((8 * c) & 63) * 256;
#pragma unroll
        for (int a = 0; a < 2; a++)
            *(uint64_t*)(bases[a] + off + tid * 8) = 0ULL;
    }
    const int fut = *futp;
    __syncthreads();
    init_bar();                                   // also resets g_ticket

    Cur C; C.pi = 0; C.ci = 0;
    float c1s[4], c2s[4];
#pragma unroll
    for (int q = 0; q < 4; q++) { c1s[q] = 0.f; c2s[q] = 0.f; }
    int p = 0;

    const char* whh1b = (const char*)gPWhh1 + (long)c * 16 * 8192;
    const char* whh2b = (const char*)gPWhh2 + (long)c * 16 * 8192;
    const char* wih2b = (const char*)gPWih2 + (long)c * 16 * 8192;
    const char* w1b   = (const char*)gPWih1 + (long)c * 8192;

    for (int t = 0; t < TSEQ; t++) {
        char* h1p = (char*)gH1T + p * 262144;
        char* h1n = (char*)gH1T + (1 - p) * 262144;
        char* h2p = (char*)gH2T + p * 262144;
        char* h2n = (char*)gH2T + (1 - p) * 262144;
        run_step(C, smb, n0,
                 (char*)gPX + (long)t * 16384,
                 h1p, h2p, h1n, h2n, w1b, whh1b, whh2b, wih2b,
                 0u, t ? BT(2 * t - 1) : 0u, t ? BT(2 * t) : 0u, BT(2 * t + 1),
                 c1s, c2s);
        p ^= 1;
    }

    wait_all(BT(2 * TSEQ));                       // B2[127]
    linear_out(Wlin, blin, c);
    bar_arrive();                                 // Lin0 = event 257

    for (int f = 0; f < fut; f++) {
        char* h1p = (char*)gH1T + p * 262144;
        char* h1n = (char*)gH1T + (1 - p) * 262144;
        char* h2p = (char*)gH2T + p * 262144;
        char* h2n = (char*)gH2T + (1 - p) * 262144;
        run_step(C, smb, n0,
                 (char*)gOutT,
                 h1p, h2p, h1n, h2n, w1b, whh1b, whh2b, wih2b,
                 BT(257 + 3 * f), BT(255 + 3 * f), BT(256 + 3 * f), BT(258 + 3 * f),
                 c1s, c2s);
        p ^= 1;
        wait_all(BT(259 + 3 * f));                // B2 of this future step
        linear_out(Whio, bhio, c);
        bar_arrive();                             // Lin_{f+1}
    }

    __syncthreads();
    for (int d = tid; d < DIN; d += NTHR)
        out[c * DIN + d] = gOut[c * DIN + d];
}

extern "C" void kernel_launch(void* const* d_in, const int* in_sizes, int n_in,
                              void* d_out, int out_size)
{
    const float* x    = (const float*)d_in[0];
    const float* Wih1 = (const float*)d_in[1];
    const float* Whh1 = (const float*)d_in[2];
    const float* bih1 = (const float*)d_in[3];
    const float* bhh1 = (const float*)d_in[4];
    const float* Wih2 = (const float*)d_in[5];
    const float* Whh2 = (const float*)d_in[6];
    const float* bih2 = (const float*)d_in[7];
    const float* bhh2 = (const float*)d_in[8];
    const float* Wlin = (const float*)d_in[9];
    const float* blin = (const float*)d_in[10];
    const float* Whio = (const float*)d_in[11];
    const float* bhio = (const float*)d_in[12];
    const int*   futp = (const int*)d_in[13];

    cudaFuncSetAttribute(lstm_hmma, cudaFuncAttributeMaxDynamicSharedMemorySize, DYN_SMEM);

    precompute<<<1024, 256>>>(x, Wih1, Whh1, bih1, bhh1, Wih2, Whh2, bih2, bhh2);
    lstm_hmma<<<GRID, NTHR, DYN_SMEM>>>(Wlin, blin, Whio, bhio, futp, (float*)d_out);
}